// round 6
// baseline (speedup 1.0000x reference)
#include <cuda_runtime.h>
#include <cuda_bf16.h>
#include <math.h>
#include <stdint.h>

// ---------------- problem constants ----------------
#define B_ 2
#define S_ 2048
#define D_ 2048
#define H_ 16
#define RK 512
#define ROPE_ 64
#define NOPE_ 128
#define QK_HD 192
#define V_HD 128
#define CD 576            // RK + ROPE
#define BS (B_ * S_)      // 4096
#define QROW (H_ * CD)    // 9216
#define QBROW (H_ * QK_HD)// 3072
#define OLROW (H_ * RK)   // 8192
#define OVROW (H_ * V_HD) // 2048
#define EPS_ 1.1920929e-07f
#define SCALE_ 0.0721687836487032f

// ---------------- scratch ----------------
__device__ float g_q   [(size_t)BS * QBROW];   // raw fp32
__device__ float g_qf  [(size_t)BS * QROW];    // tf32-rounded (flash input)
__device__ float g_kvt [(size_t)BS * CD];      // raw fp32
__device__ float g_kf  [(size_t)BS * CD];      // tf32-rounded (flash input)
__device__ float g_ol  [(size_t)BS * OLROW];   // raw fp32
__device__ float g_ov  [(size_t)BS * OVROW];   // raw fp32

// ---------------- helpers ----------------
__device__ __forceinline__ float tf32r(float x) {
    uint32_t u = __float_as_uint(x), o;
    asm("cvt.rna.tf32.f32 %0, %1;" : "=r"(o) : "r"(u));
    return __uint_as_float(o);
}
__device__ __forceinline__ void split2(float v, uint32_t& hi, uint32_t& lo) {
    float h = tf32r(v);
    hi = __float_as_uint(h);
    lo = __float_as_uint(tf32r(v - h));
}
__device__ __forceinline__ void mma_tf32(float c[4],
    uint32_t a0, uint32_t a1, uint32_t a2, uint32_t a3,
    uint32_t b0, uint32_t b1)
{
    asm volatile("mma.sync.aligned.m16n8k8.row.col.f32.tf32.tf32.f32 "
        "{%0,%1,%2,%3}, {%4,%5,%6,%7}, {%8,%9}, {%0,%1,%2,%3};\n"
        : "+f"(c[0]), "+f"(c[1]), "+f"(c[2]), "+f"(c[3])
        : "r"(a0), "r"(a1), "r"(a2), "r"(a3), "r"(b0), "r"(b1));
}

// ---------------- split-precision GEMM, LDG/STS ping-pong ----------------
// C = alpha * A*op(B) (+bias). A:(M,K) rm raw fp32. TB ? B:(N,K) rm : B:(K,N) rm.
// 128x64x16 tile. Registers hold k-tile t+1; smem double-buffered; 1 sync/k-tile.
template<bool TB, bool HASB, bool RND>
__global__ __launch_bounds__(256)
void gemm_sp(int K,
             const float* __restrict__ A, int lda, long aB,
             const float* __restrict__ Bm, int ldb, long bB,
             float* __restrict__ C, int ldc, long cB,
             const float* __restrict__ bias, float alpha)
{
    __shared__ float sA[2][2560];   // 128 rows * pitch 20
    __shared__ float sB[2][1280];   // TB: 64*20 ; non-TB: 16*72(+pad)

    int z = blockIdx.z;
    A  += (long)z * aB;
    Bm += (long)z * bB;
    C  += (long)z * cB;

    long m0 = (long)blockIdx.y * 128;
    long n0 = (long)blockIdx.x * 64;
    int tid = threadIdx.x;
    int w = tid >> 5, lane = tid & 31, gid = lane >> 2, tig = lane & 3;
    int wm = w & 3, wn = w >> 2;

    // per-thread load coords
    int aR0 = tid >> 2,          aK0 = (tid & 3) * 4;          // chunk 0
    int aR1 = (tid + 256) >> 2,  aK1 = (tid & 3) * 4;          // chunk 1
    int bR  = tid >> 2,          bK  = (tid & 3) * 4;          // TB mode
    int bKK = tid >> 4,          bN  = (tid & 15) * 4;         // non-TB mode

    float4 vA0, vA1, vB;
    auto ldg = [&](int kt) {
        int k0 = kt * 16;
        vA0 = *(const float4*)&A[(m0 + aR0) * (long)lda + k0 + aK0];
        vA1 = *(const float4*)&A[(m0 + aR1) * (long)lda + k0 + aK1];
        if (TB) vB = *(const float4*)&Bm[(n0 + bR) * (long)ldb + k0 + bK];
        else    vB = *(const float4*)&Bm[(long)(k0 + bKK) * (long)ldb + n0 + bN];
    };
    auto sts = [&](int s) {
        *(float4*)&sA[s][aR0 * 20 + aK0] = vA0;
        *(float4*)&sA[s][aR1 * 20 + aK1] = vA1;
        if (TB) *(float4*)&sB[s][bR * 20 + bK] = vB;
        else    *(float4*)&sB[s][bKK * 72 + bN] = vB;
    };

    float acc[2][4][4];
#pragma unroll
    for (int mi = 0; mi < 2; mi++)
#pragma unroll
        for (int j = 0; j < 4; j++)
#pragma unroll
            for (int e = 0; e < 4; e++) acc[mi][j][e] = 0.f;

    int nk = K / 16;
    ldg(0); sts(0);
    if (nk > 1) ldg(1);

    for (int kt = 0; kt < nk; kt++) {
        int cur = kt & 1;
        __syncthreads();
        if (kt + 1 < nk) sts(cur ^ 1);
        if (kt + 2 < nk) ldg(kt + 2);

        const float* cA = sA[cur];
        const float* cB = sB[cur];
#pragma unroll
        for (int kk = 0; kk < 2; kk++) {
            uint32_t ahi[2][4], alo[2][4], bhi[4][2], blo[4][2];
#pragma unroll
            for (int mi = 0; mi < 2; mi++) {
                int rb = wm * 32 + mi * 16 + gid;
                split2(cA[rb * 20 + kk * 8 + tig],           ahi[mi][0], alo[mi][0]);
                split2(cA[(rb + 8) * 20 + kk * 8 + tig],     ahi[mi][1], alo[mi][1]);
                split2(cA[rb * 20 + kk * 8 + tig + 4],       ahi[mi][2], alo[mi][2]);
                split2(cA[(rb + 8) * 20 + kk * 8 + tig + 4], ahi[mi][3], alo[mi][3]);
            }
#pragma unroll
            for (int j = 0; j < 4; j++) {
                int nb = wn * 32 + j * 8 + gid;
                if (TB) {
                    split2(cB[nb * 20 + kk * 8 + tig],     bhi[j][0], blo[j][0]);
                    split2(cB[nb * 20 + kk * 8 + tig + 4], bhi[j][1], blo[j][1]);
                } else {
                    split2(cB[(kk * 8 + tig) * 72 + nb],     bhi[j][0], blo[j][0]);
                    split2(cB[(kk * 8 + tig + 4) * 72 + nb], bhi[j][1], blo[j][1]);
                }
            }
#pragma unroll
            for (int mi = 0; mi < 2; mi++)
#pragma unroll
                for (int j = 0; j < 4; j++) {
                    mma_tf32(acc[mi][j], ahi[mi][0], ahi[mi][1], ahi[mi][2], ahi[mi][3],
                             blo[j][0], blo[j][1]);
                    mma_tf32(acc[mi][j], alo[mi][0], alo[mi][1], alo[mi][2], alo[mi][3],
                             bhi[j][0], bhi[j][1]);
                    mma_tf32(acc[mi][j], ahi[mi][0], ahi[mi][1], ahi[mi][2], ahi[mi][3],
                             bhi[j][0], bhi[j][1]);
                }
        }
    }

#pragma unroll
    for (int mi = 0; mi < 2; mi++) {
#pragma unroll
        for (int j = 0; j < 4; j++) {
            long col = n0 + wn * 32 + j * 8 + 2 * tig;
            float bx = 0.f, by = 0.f;
            if (HASB) { bx = bias[col]; by = bias[col + 1]; }
            long r0 = m0 + wm * 32 + mi * 16 + gid;
            float v0x = acc[mi][j][0] * alpha + bx, v0y = acc[mi][j][1] * alpha + by;
            float v1x = acc[mi][j][2] * alpha + bx, v1y = acc[mi][j][3] * alpha + by;
            if (RND) { v0x = tf32r(v0x); v0y = tf32r(v0y); v1x = tf32r(v1x); v1y = tf32r(v1y); }
            float2 v0 = { v0x, v0y }, v1 = { v1x, v1y };
            *(float2*)&C[r0 * (long)ldc + col] = v0;
            *(float2*)&C[(r0 + 8) * (long)ldc + col] = v1;
        }
    }
}

// ---------------- kv post: rmsnorm latent + rope k_pe -> g_kf (tf32) ----------------
__global__ __launch_bounds__(128)
void kv_post(const float* __restrict__ freqs, const float* __restrict__ knw)
{
    int bs = blockIdx.x;
    int s = bs & (S_ - 1);
    int tid = threadIdx.x;
    const float* row = g_kvt + (long)bs * CD;
    float*       out = g_kf  + (long)bs * CD;

    float ss = 0.f;
    for (int i = tid; i < RK; i += 128) { float v = row[i]; ss += v * v; }
    __shared__ float red[128];
    red[tid] = ss;
    __syncthreads();
    for (int o = 64; o > 0; o >>= 1) {
        if (tid < o) red[tid] += red[tid + o];
        __syncthreads();
    }
    __shared__ float rinv;
    if (tid == 0) rinv = rsqrtf(red[0] * (1.0f / RK) + EPS_);
    __syncthreads();
    float rv = rinv;
    for (int i = tid; i < RK; i += 128) out[i] = tf32r(row[i] * rv * knw[i]);

    if (tid < ROPE_ / 2) {
        float a = row[RK + 2 * tid];
        float b = row[RK + 2 * tid + 1];
        float f = freqs[(long)s * (ROPE_ / 2) + tid];
        float sn, cs;
        sincosf(f, &sn, &cs);
        out[RK + 2 * tid]     = tf32r(a * cs - b * sn);
        out[RK + 2 * tid + 1] = tf32r(a * sn + b * cs);
    }
}

// ---------------- q rope (raw in, scaled, tf32 out) ----------------
__global__ __launch_bounds__(512)
void q_rope(const float* __restrict__ freqs)
{
    int bs = blockIdx.x;
    int s = bs & (S_ - 1);
    int tid = threadIdx.x;
    int h = tid >> 5, i = tid & 31;
    const float* qr = g_q + (long)bs * QBROW + h * QK_HD + NOPE_;
    float a = qr[2 * i], b = qr[2 * i + 1];
    float f = freqs[(long)s * (ROPE_ / 2) + i];
    float sn, cs;
    sincosf(f, &sn, &cs);
    float* o = g_qf + (long)bs * QROW + h * CD + RK;
    o[2 * i]     = tf32r((a * cs - b * sn) * SCALE_);
    o[2 * i + 1] = tf32r((a * sn + b * cs) * SCALE_);
}

// ---------------- flash MQA (single-tf32, LDG/STS loads) ----------------
// Block: 4 tokens x 16 heads = 64 q-rows. TK=32 keys/tile.
// smem: sq 64x580 rm, sk 32x580 rm (V = cols 0..511), sP 64x36 (stats cols 32..34).
// Scores: warps 0..1, each 32 rows x 32 keys (B-frags shared across 2 m-tiles).
// PV: all 8 warps, each 64 rows x 64 V-cols.
#define FP 580
#define SQF (64 * FP)
#define SKF (32 * FP)
#define SPF (64 * 36)
#define FLASH_FLOATS (SQF + SKF + SPF)   // 231936 B

__global__ __launch_bounds__(256, 1)
void flash_tc()
{
    extern __shared__ float fs[];
    float* sq = fs;
    float* sk = sq + SQF;
    float* sP = sk + SKF;

    int qs = blockIdx.x * 4;
    int b  = blockIdx.y;
    int tid = threadIdx.x;
    int w = tid >> 5, lane = tid & 31, gid = lane >> 2, tig = lane & 3;

    const float* qb = g_qf + ((long)(b * S_ + qs)) * QROW;
    const float* kb = g_kf + (long)b * S_ * CD;

    // ---- prologue: q tile (64 x 576) ----
    for (int c = tid; c < 64 * 144; c += 256) {
        int row = c / 144, cq = (c % 144) * 4;
        int tok = row >> 4, h = row & 15;
        *(float4*)&sq[row * FP + cq] =
            *(const float4*)&qb[(long)tok * QROW + h * CD + cq];
    }
    if (tid < 64) { sP[tid * 36 + 32] = -3.0e38f; sP[tid * 36 + 33] = 0.f; }

    float oacc[4][8][4];
#pragma unroll
    for (int rg = 0; rg < 4; rg++)
#pragma unroll
        for (int j = 0; j < 8; j++)
#pragma unroll
            for (int e = 0; e < 4; e++) oacc[rg][j][e] = 0.f;

    int ntk = qs / 32 + 1;

    for (int kt = 0; kt < ntk; kt++) {
        int t0 = kt * 32;
        __syncthreads();                 // prev PV done -> sk free (also orders sq/stats on kt=0)
        for (int c = tid; c < 32 * 144; c += 256) {
            int r = c / 144, cq = (c % 144) * 4;
            *(float4*)&sk[r * FP + cq] =
                *(const float4*)&kb[(long)(t0 + r) * CD + cq];
        }
        __syncthreads();

        // ---- scores: warps 0..1, 32 rows x 32 keys each ----
        if (w < 2) {
            int rb0 = w * 32;
            float sc[2][4][4];
#pragma unroll
            for (int mi = 0; mi < 2; mi++)
#pragma unroll
                for (int j = 0; j < 4; j++)
#pragma unroll
                    for (int e = 0; e < 4; e++) sc[mi][j][e] = 0.f;
#pragma unroll 4
            for (int kk = 0; kk < 72; kk++) {
                int kc = kk * 8;
                uint32_t a[2][4];
#pragma unroll
                for (int mi = 0; mi < 2; mi++) {
                    int r0 = rb0 + mi * 16 + gid;
                    a[mi][0] = __float_as_uint(sq[r0 * FP + kc + tig]);
                    a[mi][1] = __float_as_uint(sq[(r0 + 8) * FP + kc + tig]);
                    a[mi][2] = __float_as_uint(sq[r0 * FP + kc + tig + 4]);
                    a[mi][3] = __float_as_uint(sq[(r0 + 8) * FP + kc + tig + 4]);
                }
#pragma unroll
                for (int j = 0; j < 4; j++) {
                    uint32_t b0 = __float_as_uint(sk[(j * 8 + gid) * FP + kc + tig]);
                    uint32_t b1 = __float_as_uint(sk[(j * 8 + gid) * FP + kc + tig + 4]);
                    mma_tf32(sc[0][j], a[0][0], a[0][1], a[0][2], a[0][3], b0, b1);
                    mma_tf32(sc[1][j], a[1][0], a[1][1], a[1][2], a[1][3], b0, b1);
                }
            }
#pragma unroll
            for (int mi = 0; mi < 2; mi++)
#pragma unroll
                for (int j = 0; j < 4; j++) {
                    int r0 = rb0 + mi * 16 + gid;
                    int c0 = j * 8 + 2 * tig;
                    float2 v0 = { sc[mi][j][0], sc[mi][j][1] };
                    float2 v1 = { sc[mi][j][2], sc[mi][j][3] };
                    *(float2*)&sP[r0 * 36 + c0] = v0;
                    *(float2*)&sP[(r0 + 8) * 36 + c0] = v1;
                }
        }
        __syncthreads();

        // ---- online softmax (64 threads, one row each); causal mask here ----
        if (tid < 64) {
            int row = tid;
            int spos = qs + (row >> 4);
            float* pr = sP + row * 36;
            float v[32];
            float mo = pr[32], mx = mo;
#pragma unroll
            for (int j = 0; j < 32; j++) {
                float x = pr[j];
                if (t0 + j > spos) x = -1.0e30f;
                v[j] = x;
                mx = fmaxf(mx, x);
            }
            float al = __expf(mo - mx);
            float sum = 0.f;
#pragma unroll
            for (int j = 0; j < 32; j++) {
                float p = __expf(v[j] - mx);
                sum += p;
                pr[j] = tf32r(p);
            }
            pr[32] = mx;
            pr[33] = pr[33] * al + sum;
            pr[34] = al;
        }
        __syncthreads();

        // ---- PV: all 8 warps, 64 rows x 64 V-cols each ----
        {
            float al0[4], al1[4];
#pragma unroll
            for (int rg = 0; rg < 4; rg++) {
                al0[rg] = sP[(rg * 16 + gid) * 36 + 34];
                al1[rg] = sP[(rg * 16 + gid + 8) * 36 + 34];
            }
#pragma unroll
            for (int rg = 0; rg < 4; rg++)
#pragma unroll
                for (int j = 0; j < 8; j++) {
                    oacc[rg][j][0] *= al0[rg]; oacc[rg][j][1] *= al0[rg];
                    oacc[rg][j][2] *= al1[rg]; oacc[rg][j][3] *= al1[rg];
                }
#pragma unroll
            for (int kk = 0; kk < 4; kk++) {
                int kc = kk * 8;
                uint32_t A0[4], A1[4], A2[4], A3[4];
#pragma unroll
                for (int rg = 0; rg < 4; rg++) {
                    A0[rg] = __float_as_uint(sP[(rg * 16 + gid) * 36 + kc + tig]);
                    A1[rg] = __float_as_uint(sP[(rg * 16 + gid + 8) * 36 + kc + tig]);
                    A2[rg] = __float_as_uint(sP[(rg * 16 + gid) * 36 + kc + tig + 4]);
                    A3[rg] = __float_as_uint(sP[(rg * 16 + gid + 8) * 36 + kc + tig + 4]);
                }
#pragma unroll
                for (int j = 0; j < 8; j++) {
                    int col = w * 64 + j * 8 + gid;
                    uint32_t b0 = __float_as_uint(sk[(kc + tig) * FP + col]);
                    uint32_t b1 = __float_as_uint(sk[(kc + tig + 4) * FP + col]);
#pragma unroll
                    for (int rg = 0; rg < 4; rg++)
                        mma_tf32(oacc[rg][j], A0[rg], A1[rg], A2[rg], A3[rg], b0, b1);
                }
            }
        }
    }

    // ---- epilogue: normalize + write raw fp32 ----
#pragma unroll
    for (int rg = 0; rg < 4; rg++) {
        float l0 = 1.f / sP[(rg * 16 + gid) * 36 + 33];
        float l1 = 1.f / sP[(rg * 16 + gid + 8) * 36 + 33];
        long base = ((long)(b * S_ + qs + rg)) * OLROW;
        float* o0 = g_ol + base + (long)gid * RK + w * 64;
        float* o1 = g_ol + base + (long)(gid + 8) * RK + w * 64;
#pragma unroll
        for (int j = 0; j < 8; j++) {
            int col = j * 8 + 2 * tig;
            float2 v0 = { oacc[rg][j][0] * l0, oacc[rg][j][1] * l0 };
            float2 v1 = { oacc[rg][j][2] * l1, oacc[rg][j][3] * l1 };
            *(float2*)&o0[col] = v0;
            *(float2*)&o1[col] = v1;
        }
    }
}

// ---------------- launch ----------------
extern "C" void kernel_launch(void* const* d_in, const int* in_sizes, int n_in,
                              void* d_out, int out_size)
{
    const float* x      = (const float*)d_in[0];
    const float* freqs  = (const float*)d_in[1];
    // d_in[2] = mask (causal handled analytically)
    const float* wq_w   = (const float*)d_in[3];
    const float* wq_b   = (const float*)d_in[4];
    const float* wkva_w = (const float*)d_in[5];
    const float* wkva_b = (const float*)d_in[6];
    const float* knw    = (const float*)d_in[7];
    const float* wkvb   = (const float*)d_in[8];
    const float* wo_w   = (const float*)d_in[9];
    const float* wo_b   = (const float*)d_in[10];
    float* out = (float*)d_out;

    float *pq, *pqf, *pkv, *pol, *pov;
    cudaGetSymbolAddress((void**)&pq,  g_q);
    cudaGetSymbolAddress((void**)&pqf, g_qf);
    cudaGetSymbolAddress((void**)&pkv, g_kvt);
    cudaGetSymbolAddress((void**)&pol, g_ol);
    cudaGetSymbolAddress((void**)&pov, g_ov);

    const int FLASH_SMEM = FLASH_FLOATS * (int)sizeof(float); // 231936
    cudaFuncSetAttribute(flash_tc, cudaFuncAttributeMaxDynamicSharedMemorySize, FLASH_SMEM);

    // 1) kv = x @ wkv_a_w^T + b : (4096, 576)
    gemm_sp<true, true, false><<<dim3(CD / 64, BS / 128, 1), 256>>>(
        D_, x, D_, 0, wkva_w, D_, 0, pkv, CD, 0, wkva_b, 1.f);

    // 2) rmsnorm latent + rope k_pe -> g_kf (tf32 out for flash)
    kv_post<<<BS, 128>>>(freqs, knw);

    // 3) q = x @ wq_w^T + b : (4096, 3072)
    gemm_sp<true, true, false><<<dim3(QBROW / 64, BS / 128, 1), 256>>>(
        D_, x, D_, 0, wq_w, D_, 0, pq, QBROW, 0, wq_b, 1.f);

    // 4) rope q_pe (scaled, tf32 out) -> g_qf[..., 512:576]
    q_rope<<<BS, 512>>>(freqs);

    // 5) q_absorbed per head: q_nope @ wkv_b_nope (K,N), scaled, tf32 out for flash
    gemm_sp<false, false, true><<<dim3(RK / 64, BS / 128, H_), 256>>>(
        NOPE_, pq, QBROW, QK_HD,
        wkvb, RK, (long)(NOPE_ + V_HD) * RK,
        pqf, QROW, CD, nullptr, SCALE_);

    // 6) causal flash MQA -> g_ol (raw fp32)
    flash_tc<<<dim3(S_ / 4, B_), 256, FLASH_SMEM>>>();

    // 7) per-head V up-projection: o_lat @ wkv_b_v^T -> g_ov (raw)
    gemm_sp<true, false, false><<<dim3(V_HD / 64, BS / 128, H_), 256>>>(
        RK, pol, OLROW, RK,
        wkvb + (long)NOPE_ * RK, RK, (long)(NOPE_ + V_HD) * RK,
        pov, OVROW, V_HD, nullptr, 1.f);

    // 8) final: g_ov @ wo_w^T + wo_b -> out (fp32)
    gemm_sp<true, true, false><<<dim3(D_ / 64, BS / 128, 1), 256>>>(
        OVROW, pov, OVROW, 0, wo_w, D_, 0, out, D_, 0, wo_b, 1.f);
}

// round 7
// speedup vs baseline: 1.4388x; 1.4388x over previous
#include <cuda_runtime.h>
#include <cuda_bf16.h>
#include <math.h>
#include <stdint.h>

// ---------------- problem constants ----------------
#define B_ 2
#define S_ 2048
#define D_ 2048
#define H_ 16
#define RK 512
#define ROPE_ 64
#define NOPE_ 128
#define QK_HD 192
#define V_HD 128
#define CD 576            // RK + ROPE
#define BS (B_ * S_)      // 4096
#define QROW (H_ * CD)    // 9216
#define QBROW (H_ * QK_HD)// 3072
#define OLROW (H_ * RK)   // 8192
#define OVROW (H_ * V_HD) // 2048
#define EPS_ 1.1920929e-07f
#define SCALE_ 0.0721687836487032f

// ---------------- scratch ----------------
__device__ float g_q   [(size_t)BS * QBROW];   // raw fp32
__device__ float g_qf  [(size_t)BS * QROW];    // tf32-rounded (flash input)
__device__ float g_kvt [(size_t)BS * CD];      // raw fp32
__device__ float g_kf  [(size_t)BS * CD];      // tf32-rounded (flash input)
__device__ float g_ol  [(size_t)BS * OLROW];   // raw fp32
__device__ float g_ov  [(size_t)BS * OVROW];   // raw fp32

// ---------------- helpers ----------------
__device__ __forceinline__ float tf32r(float x) {
    uint32_t u = __float_as_uint(x), o;
    asm("cvt.rna.tf32.f32 %0, %1;" : "=r"(o) : "r"(u));
    return __uint_as_float(o);
}
// split a float2 (adjacent k) into packed bf16x2 hi and lo parts
__device__ __forceinline__ void split_bf2(float2 p, uint32_t& hi, uint32_t& lo) {
    __nv_bfloat162 h = __float22bfloat162_rn(p);
    float hx = __low2float(h), hy = __high2float(h);
    float2 pl = make_float2(p.x - hx, p.y - hy);
    __nv_bfloat162 l = __float22bfloat162_rn(pl);
    hi = *(uint32_t*)&h;
    lo = *(uint32_t*)&l;
}
__device__ __forceinline__ void mma_bf16(float c[4],
    uint32_t a0, uint32_t a1, uint32_t a2, uint32_t a3,
    uint32_t b0, uint32_t b1)
{
    asm volatile("mma.sync.aligned.m16n8k16.row.col.f32.bf16.bf16.f32 "
        "{%0,%1,%2,%3}, {%4,%5,%6,%7}, {%8,%9}, {%0,%1,%2,%3};\n"
        : "+f"(c[0]), "+f"(c[1]), "+f"(c[2]), "+f"(c[3])
        : "r"(a0), "r"(a1), "r"(a2), "r"(a3), "r"(b0), "r"(b1));
}
__device__ __forceinline__ void mma_tf32(float c[4],
    uint32_t a0, uint32_t a1, uint32_t a2, uint32_t a3,
    uint32_t b0, uint32_t b1)
{
    asm volatile("mma.sync.aligned.m16n8k8.row.col.f32.tf32.tf32.f32 "
        "{%0,%1,%2,%3}, {%4,%5,%6,%7}, {%8,%9}, {%0,%1,%2,%3};\n"
        : "+f"(c[0]), "+f"(c[1]), "+f"(c[2]), "+f"(c[3])
        : "r"(a0), "r"(a1), "r"(a2), "r"(a3), "r"(b0), "r"(b1));
}
__device__ __forceinline__ uint32_t sm_u32(const void* p) {
    return (uint32_t)__cvta_generic_to_shared(p);
}
#define CPA16(d, s) asm volatile("cp.async.ca.shared.global [%0], [%1], 16;\n" :: "r"(d), "l"(s))
#define CPCOMMIT()  asm volatile("cp.async.commit_group;\n")
#define CPWAIT(n)   asm volatile("cp.async.wait_group %0;\n" :: "n"(n))

// ---------------- bf16-split pipelined GEMM (near-fp32 accurate) ----------------
// C = alpha * A*op(B) (+bias). A:(M,K) rm raw fp32. TB ? B:(N,K) rm : B:(K,N) rm.
// 128x64x16 tile, 3-stage cp.async. Fragments split into bf16 hi/lo;
// 3x mma.m16n8k16 (hi*lo + lo*hi + hi*hi) per 16-deep chunk.
#define GA_ST 3072            // 128 * 24 floats per A stage
#define GB_ST 1536            // max(64*24, 16*72)
#define GEMM_SMEM ((3 * (GA_ST + GB_ST)) * 4)   // 55296 B dynamic
template<bool TB, bool HASB, bool RND>
__global__ __launch_bounds__(256)
void gemm_bs(int K,
             const float* __restrict__ A, int lda, long aB,
             const float* __restrict__ Bm, int ldb, long bB,
             float* __restrict__ C, int ldc, long cB,
             const float* __restrict__ bias, float alpha)
{
    extern __shared__ float gsm[];
    float* sA = gsm;                  // 3 stages, pitch 24
    float* sB = gsm + 3 * GA_ST;      // 3 stages

    int z = blockIdx.z;
    A  += (long)z * aB;
    Bm += (long)z * bB;
    C  += (long)z * cB;

    long m0 = (long)blockIdx.y * 128;
    long n0 = (long)blockIdx.x * 64;
    int tid = threadIdx.x;
    int w = tid >> 5, lane = tid & 31, gid = lane >> 2, tig = lane & 3;
    int wm = w & 3, wn = w >> 2;

    uint32_t sAu = sm_u32(sA), sBu = sm_u32(sB);
    int nk = K / 16;

    auto issue = [&](int s, int kt) {
        int k0 = kt * 16;
#pragma unroll
        for (int i = 0; i < 2; i++) {
            int c = tid + i * 256;
            int r = c >> 2, kq = (c & 3) * 4;
            CPA16(sAu + (s * GA_ST + r * 24 + kq) * 4,
                  &A[(m0 + r) * (long)lda + k0 + kq]);
        }
        if (TB) {
            int r = tid >> 2, kq = (tid & 3) * 4;
            CPA16(sBu + (s * GB_ST + r * 24 + kq) * 4,
                  &Bm[(n0 + r) * (long)ldb + k0 + kq]);
        } else {
            int kk = tid >> 4, nq = (tid & 15) * 4;
            CPA16(sBu + (s * GB_ST + kk * 72 + nq) * 4,
                  &Bm[(long)(k0 + kk) * (long)ldb + n0 + nq]);
        }
    };

    float acc[2][4][4];
#pragma unroll
    for (int mi = 0; mi < 2; mi++)
#pragma unroll
        for (int j = 0; j < 4; j++)
#pragma unroll
            for (int e = 0; e < 4; e++) acc[mi][j][e] = 0.f;

    issue(0, 0); CPCOMMIT();
    if (nk > 1) { issue(1, 1); CPCOMMIT(); }

    for (int kt = 0; kt < nk; kt++) {
        CPWAIT(1);
        __syncthreads();
        if (kt + 2 < nk) { issue((kt + 2) % 3, kt + 2); CPCOMMIT(); }

        const float* cA = sA + (kt % 3) * GA_ST;
        const float* cB = sB + (kt % 3) * GB_ST;

        // one 16-deep bf16 chunk per k-tile
        uint32_t ahi[2][4], alo[2][4], bhi[4][2], blo[4][2];
#pragma unroll
        for (int mi = 0; mi < 2; mi++) {
            int rb = wm * 32 + mi * 16 + gid;
            split_bf2(*(const float2*)&cA[rb * 24 + 2 * tig],           ahi[mi][0], alo[mi][0]);
            split_bf2(*(const float2*)&cA[(rb + 8) * 24 + 2 * tig],     ahi[mi][1], alo[mi][1]);
            split_bf2(*(const float2*)&cA[rb * 24 + 2 * tig + 8],       ahi[mi][2], alo[mi][2]);
            split_bf2(*(const float2*)&cA[(rb + 8) * 24 + 2 * tig + 8], ahi[mi][3], alo[mi][3]);
        }
#pragma unroll
        for (int j = 0; j < 4; j++) {
            int nb = wn * 32 + j * 8 + gid;
            if (TB) {
                split_bf2(*(const float2*)&cB[nb * 24 + 2 * tig],     bhi[j][0], blo[j][0]);
                split_bf2(*(const float2*)&cB[nb * 24 + 2 * tig + 8], bhi[j][1], blo[j][1]);
            } else {
                float2 q0 = make_float2(cB[(2 * tig) * 72 + nb],     cB[(2 * tig + 1) * 72 + nb]);
                float2 q1 = make_float2(cB[(2 * tig + 8) * 72 + nb], cB[(2 * tig + 9) * 72 + nb]);
                split_bf2(q0, bhi[j][0], blo[j][0]);
                split_bf2(q1, bhi[j][1], blo[j][1]);
            }
        }
#pragma unroll
        for (int mi = 0; mi < 2; mi++)
#pragma unroll
            for (int j = 0; j < 4; j++) {
                mma_bf16(acc[mi][j], ahi[mi][0], ahi[mi][1], ahi[mi][2], ahi[mi][3],
                         blo[j][0], blo[j][1]);
                mma_bf16(acc[mi][j], alo[mi][0], alo[mi][1], alo[mi][2], alo[mi][3],
                         bhi[j][0], bhi[j][1]);
                mma_bf16(acc[mi][j], ahi[mi][0], ahi[mi][1], ahi[mi][2], ahi[mi][3],
                         bhi[j][0], bhi[j][1]);
            }
        __syncthreads();
    }

#pragma unroll
    for (int mi = 0; mi < 2; mi++) {
#pragma unroll
        for (int j = 0; j < 4; j++) {
            long col = n0 + wn * 32 + j * 8 + 2 * tig;
            float bx = 0.f, by = 0.f;
            if (HASB) { bx = bias[col]; by = bias[col + 1]; }
            long r0 = m0 + wm * 32 + mi * 16 + gid;
            float v0x = acc[mi][j][0] * alpha + bx, v0y = acc[mi][j][1] * alpha + by;
            float v1x = acc[mi][j][2] * alpha + bx, v1y = acc[mi][j][3] * alpha + by;
            if (RND) { v0x = tf32r(v0x); v0y = tf32r(v0y); v1x = tf32r(v1x); v1y = tf32r(v1y); }
            float2 v0 = { v0x, v0y }, v1 = { v1x, v1y };
            *(float2*)&C[r0 * (long)ldc + col] = v0;
            *(float2*)&C[(r0 + 8) * (long)ldc + col] = v1;
        }
    }
}

// ---------------- kv post: rmsnorm latent + rope k_pe -> g_kf (tf32) ----------------
__global__ __launch_bounds__(128)
void kv_post(const float* __restrict__ freqs, const float* __restrict__ knw)
{
    int bs = blockIdx.x;
    int s = bs & (S_ - 1);
    int tid = threadIdx.x;
    const float* row = g_kvt + (long)bs * CD;
    float*       out = g_kf  + (long)bs * CD;

    float ss = 0.f;
    for (int i = tid; i < RK; i += 128) { float v = row[i]; ss += v * v; }
    __shared__ float red[128];
    red[tid] = ss;
    __syncthreads();
    for (int o = 64; o > 0; o >>= 1) {
        if (tid < o) red[tid] += red[tid + o];
        __syncthreads();
    }
    __shared__ float rinv;
    if (tid == 0) rinv = rsqrtf(red[0] * (1.0f / RK) + EPS_);
    __syncthreads();
    float rv = rinv;
    for (int i = tid; i < RK; i += 128) out[i] = tf32r(row[i] * rv * knw[i]);

    if (tid < ROPE_ / 2) {
        float a = row[RK + 2 * tid];
        float b = row[RK + 2 * tid + 1];
        float f = freqs[(long)s * (ROPE_ / 2) + tid];
        float sn, cs;
        sincosf(f, &sn, &cs);
        out[RK + 2 * tid]     = tf32r(a * cs - b * sn);
        out[RK + 2 * tid + 1] = tf32r(a * sn + b * cs);
    }
}

// ---------------- q rope (raw in, scaled, tf32 out) ----------------
__global__ __launch_bounds__(512)
void q_rope(const float* __restrict__ freqs)
{
    int bs = blockIdx.x;
    int s = bs & (S_ - 1);
    int tid = threadIdx.x;
    int h = tid >> 5, i = tid & 31;
    const float* qr = g_q + (long)bs * QBROW + h * QK_HD + NOPE_;
    float a = qr[2 * i], b = qr[2 * i + 1];
    float f = freqs[(long)s * (ROPE_ / 2) + i];
    float sn, cs;
    sincosf(f, &sn, &cs);
    float* o = g_qf + (long)bs * QROW + h * CD + RK;
    o[2 * i]     = tf32r((a * cs - b * sn) * SCALE_);
    o[2 * i + 1] = tf32r((a * sn + b * cs) * SCALE_);
}

// ---------------- flash MQA (single-tf32, cp.async) — R4 configuration ----------------
// Block: 4 tokens x 16 heads = 64 q-rows. TK=32 keys per tile.
// smem: sq 64x580 rm, sk 32x580 rm (V = cols 0..511), sP 64x36 (stats cols 32..34).
// Scores: warps 0..3, 16 rows x 32 keys each, 72 k8 steps.
// PV: all 8 warps, each 64 rows x 64 V-cols.
#define FP 580
#define SQF (64 * FP)
#define SKF (32 * FP)
#define SPF (64 * 36)
#define FLASH_FLOATS (SQF + SKF + SPF)   // 231936 B

__global__ __launch_bounds__(256, 1)
void flash_tc()
{
    extern __shared__ float fs[];
    float* sq = fs;
    float* sk = sq + SQF;
    float* sP = sk + SKF;

    int qs = blockIdx.x * 4;
    int b  = blockIdx.y;
    int tid = threadIdx.x;
    int w = tid >> 5, lane = tid & 31, gid = lane >> 2, tig = lane & 3;

    uint32_t squ = sm_u32(sq), sku = sm_u32(sk);
    const float* qb = g_qf + ((long)(b * S_ + qs)) * QROW;
    const float* kb = g_kf + (long)b * S_ * CD;

    for (int c = tid; c < 64 * 144; c += 256) {
        int row = c / 144, cq = (c % 144) * 4;
        int tok = row >> 4, h = row & 15;
        CPA16(squ + (row * FP + cq) * 4, &qb[(long)tok * QROW + h * CD + cq]);
    }
    for (int c = tid; c < 32 * 144; c += 256) {
        int r = c / 144, cq = (c % 144) * 4;
        CPA16(sku + (r * FP + cq) * 4, &kb[(long)r * CD + cq]);
    }
    CPCOMMIT();
    if (tid < 64) { sP[tid * 36 + 32] = -3.0e38f; sP[tid * 36 + 33] = 0.f; }

    float oacc[4][8][4];
#pragma unroll
    for (int rg = 0; rg < 4; rg++)
#pragma unroll
        for (int j = 0; j < 8; j++)
#pragma unroll
            for (int e = 0; e < 4; e++) oacc[rg][j][e] = 0.f;

    int ntk = qs / 32 + 1;

    for (int kt = 0; kt < ntk; kt++) {
        int t0 = kt * 32;
        CPWAIT(0);
        __syncthreads();

        if (w < 4) {
            int rb = w * 16;
            const float* r0p = sq + (rb + gid) * FP;
            const float* r1p = sq + (rb + gid + 8) * FP;
            float sc[4][4];
#pragma unroll
            for (int j = 0; j < 4; j++)
#pragma unroll
                for (int e = 0; e < 4; e++) sc[j][e] = 0.f;
#pragma unroll 8
            for (int kk = 0; kk < 72; kk++) {
                int kc = kk * 8;
                uint32_t a0 = __float_as_uint(r0p[kc + tig]);
                uint32_t a1 = __float_as_uint(r1p[kc + tig]);
                uint32_t a2 = __float_as_uint(r0p[kc + tig + 4]);
                uint32_t a3 = __float_as_uint(r1p[kc + tig + 4]);
#pragma unroll
                for (int j = 0; j < 4; j++) {
                    uint32_t b0 = __float_as_uint(sk[(j * 8 + gid) * FP + kc + tig]);
                    uint32_t b1 = __float_as_uint(sk[(j * 8 + gid) * FP + kc + tig + 4]);
                    mma_tf32(sc[j], a0, a1, a2, a3, b0, b1);
                }
            }
#pragma unroll
            for (int j = 0; j < 4; j++) {
                int c0 = j * 8 + 2 * tig;
                float2 v0 = { sc[j][0], sc[j][1] };
                float2 v1 = { sc[j][2], sc[j][3] };
                *(float2*)&sP[(rb + gid) * 36 + c0] = v0;
                *(float2*)&sP[(rb + gid + 8) * 36 + c0] = v1;
            }
        }
        __syncthreads();

        if (tid < 64) {
            int row = tid;
            int spos = qs + (row >> 4);
            float* pr = sP + row * 36;
            float v[32];
            float mo = pr[32], mx = mo;
#pragma unroll
            for (int j = 0; j < 32; j++) {
                float x = pr[j];
                if (t0 + j > spos) x = -1.0e30f;
                v[j] = x;
                mx = fmaxf(mx, x);
            }
            float al = __expf(mo - mx);
            float sum = 0.f;
#pragma unroll
            for (int j = 0; j < 32; j++) {
                float p = __expf(v[j] - mx);
                sum += p;
                pr[j] = tf32r(p);
            }
            pr[32] = mx;
            pr[33] = pr[33] * al + sum;
            pr[34] = al;
        }
        __syncthreads();

        {
            float al0[4], al1[4];
#pragma unroll
            for (int rg = 0; rg < 4; rg++) {
                al0[rg] = sP[(rg * 16 + gid) * 36 + 34];
                al1[rg] = sP[(rg * 16 + gid + 8) * 36 + 34];
            }
#pragma unroll
            for (int rg = 0; rg < 4; rg++)
#pragma unroll
                for (int j = 0; j < 8; j++) {
                    oacc[rg][j][0] *= al0[rg]; oacc[rg][j][1] *= al0[rg];
                    oacc[rg][j][2] *= al1[rg]; oacc[rg][j][3] *= al1[rg];
                }
#pragma unroll
            for (int kk = 0; kk < 4; kk++) {
                int kc = kk * 8;
                uint32_t A0[4], A1[4], A2[4], A3[4];
#pragma unroll
                for (int rg = 0; rg < 4; rg++) {
                    A0[rg] = __float_as_uint(sP[(rg * 16 + gid) * 36 + kc + tig]);
                    A1[rg] = __float_as_uint(sP[(rg * 16 + gid + 8) * 36 + kc + tig]);
                    A2[rg] = __float_as_uint(sP[(rg * 16 + gid) * 36 + kc + tig + 4]);
                    A3[rg] = __float_as_uint(sP[(rg * 16 + gid + 8) * 36 + kc + tig + 4]);
                }
#pragma unroll
                for (int j = 0; j < 8; j++) {
                    int col = w * 64 + j * 8 + gid;
                    uint32_t b0 = __float_as_uint(sk[(kc + tig) * FP + col]);
                    uint32_t b1 = __float_as_uint(sk[(kc + tig + 4) * FP + col]);
#pragma unroll
                    for (int rg = 0; rg < 4; rg++)
                        mma_tf32(oacc[rg][j], A0[rg], A1[rg], A2[rg], A3[rg], b0, b1);
                }
            }
        }
        __syncthreads();

        if (kt + 1 < ntk) {
            int tn = t0 + 32;
            for (int c = tid; c < 32 * 144; c += 256) {
                int r = c / 144, cq = (c % 144) * 4;
                CPA16(sku + (r * FP + cq) * 4, &kb[(long)(tn + r) * CD + cq]);
            }
        }
        CPCOMMIT();
    }

    // epilogue: normalize + write raw fp32
#pragma unroll
    for (int rg = 0; rg < 4; rg++) {
        float l0 = 1.f / sP[(rg * 16 + gid) * 36 + 33];
        float l1 = 1.f / sP[(rg * 16 + gid + 8) * 36 + 33];
        long base = ((long)(b * S_ + qs + rg)) * OLROW;
        float* o0 = g_ol + base + (long)gid * RK + w * 64;
        float* o1 = g_ol + base + (long)(gid + 8) * RK + w * 64;
#pragma unroll
        for (int j = 0; j < 8; j++) {
            int col = j * 8 + 2 * tig;
            float2 v0 = { oacc[rg][j][0] * l0, oacc[rg][j][1] * l0 };
            float2 v1 = { oacc[rg][j][2] * l1, oacc[rg][j][3] * l1 };
            *(float2*)&o0[col] = v0;
            *(float2*)&o1[col] = v1;
        }
    }
}

// ---------------- launch ----------------
extern "C" void kernel_launch(void* const* d_in, const int* in_sizes, int n_in,
                              void* d_out, int out_size)
{
    const float* x      = (const float*)d_in[0];
    const float* freqs  = (const float*)d_in[1];
    // d_in[2] = mask (causal handled analytically)
    const float* wq_w   = (const float*)d_in[3];
    const float* wq_b   = (const float*)d_in[4];
    const float* wkva_w = (const float*)d_in[5];
    const float* wkva_b = (const float*)d_in[6];
    const float* knw    = (const float*)d_in[7];
    const float* wkvb   = (const float*)d_in[8];
    const float* wo_w   = (const float*)d_in[9];
    const float* wo_b   = (const float*)d_in[10];
    float* out = (float*)d_out;

    float *pq, *pqf, *pkv, *pol, *pov;
    cudaGetSymbolAddress((void**)&pq,  g_q);
    cudaGetSymbolAddress((void**)&pqf, g_qf);
    cudaGetSymbolAddress((void**)&pkv, g_kvt);
    cudaGetSymbolAddress((void**)&pol, g_ol);
    cudaGetSymbolAddress((void**)&pov, g_ov);

    const int FLASH_SMEM = FLASH_FLOATS * (int)sizeof(float); // 231936
    cudaFuncSetAttribute(flash_tc, cudaFuncAttributeMaxDynamicSharedMemorySize, FLASH_SMEM);
    cudaFuncSetAttribute(gemm_bs<true, true, false>,
                         cudaFuncAttributeMaxDynamicSharedMemorySize, GEMM_SMEM);
    cudaFuncSetAttribute(gemm_bs<false, false, true>,
                         cudaFuncAttributeMaxDynamicSharedMemorySize, GEMM_SMEM);
    cudaFuncSetAttribute(gemm_bs<true, false, false>,
                         cudaFuncAttributeMaxDynamicSharedMemorySize, GEMM_SMEM);

    // 1) kv = x @ wkv_a_w^T + b : (4096, 576)
    gemm_bs<true, true, false><<<dim3(CD / 64, BS / 128, 1), 256, GEMM_SMEM>>>(
        D_, x, D_, 0, wkva_w, D_, 0, pkv, CD, 0, wkva_b, 1.f);

    // 2) rmsnorm latent + rope k_pe -> g_kf (tf32 out for flash)
    kv_post<<<BS, 128>>>(freqs, knw);

    // 3) q = x @ wq_w^T + b : (4096, 3072)
    gemm_bs<true, true, false><<<dim3(QBROW / 64, BS / 128, 1), 256, GEMM_SMEM>>>(
        D_, x, D_, 0, wq_w, D_, 0, pq, QBROW, 0, wq_b, 1.f);

    // 4) rope q_pe (scaled, tf32 out) -> g_qf[..., 512:576]
    q_rope<<<BS, 512>>>(freqs);

    // 5) q_absorbed per head: q_nope @ wkv_b_nope (K,N), scaled, tf32 out for flash
    gemm_bs<false, false, true><<<dim3(RK / 64, BS / 128, H_), 256, GEMM_SMEM>>>(
        NOPE_, pq, QBROW, QK_HD,
        wkvb, RK, (long)(NOPE_ + V_HD) * RK,
        pqf, QROW, CD, nullptr, SCALE_);

    // 6) causal flash MQA -> g_ol (raw fp32)
    flash_tc<<<dim3(S_ / 4, B_), 256, FLASH_SMEM>>>();

    // 7) per-head V up-projection: o_lat @ wkv_b_v^T -> g_ov (raw)
    gemm_bs<true, false, false><<<dim3(V_HD / 64, BS / 128, H_), 256, GEMM_SMEM>>>(
        RK, pol, OLROW, RK,
        wkvb + (long)NOPE_ * RK, RK, (long)(NOPE_ + V_HD) * RK,
        pov, OVROW, V_HD, nullptr, 1.f);

    // 8) final: g_ov @ wo_w^T + wo_b -> out (fp32)
    gemm_bs<true, true, false><<<dim3(D_ / 64, BS / 128, 1), 256, GEMM_SMEM>>>(
        OVROW, pov, OVROW, 0, wo_w, D_, 0, out, D_, 0, wo_b, 1.f);
}